// round 5
// baseline (speedup 1.0000x reference)
#include <cuda_runtime.h>

#define VIEWS 512
#define DETS  512
#define H_IMG 256
#define W_IMG 256

#define N_PROD 128
#define N_CONS 2048

// ---- constants (computed in double, used as float) ----
static constexpr double dPI     = 3.14159265358979323846;
static constexpr double dS2R    = 5.95;
static constexpr double dD2R    = 4.906;
static constexpr double dD_DET  = 0.0072;
static constexpr double dVIRDET = dD_DET * dS2R / (dS2R + dD2R);
static constexpr double dD_IMG  = 0.006641;
static constexpr double dD_ANG  = 2.0 * dPI / (double)VIEWS;

// filtered sinogram scratch: row = b*VIEWS + v, col = det
static __device__ float g_filtered[2 * VIEWS * DETS];
// per-producer completion flags (producer pid covers rows [8*pid, 8*pid+8))
static __device__ int   g_done[N_PROD];

__global__ void reset_kernel() {
    if (threadIdx.x < N_PROD) g_done[threadIdx.x] = 0;
}

// ============================================================================
// Fused kernel.
//  bids [0, 128): PRODUCERS — weight + ramp filter for 8 sinogram rows each.
//    Ramp filter is nonzero only at the center tap and odd offsets, i.e. at
//    even filt indices. With Ge[n] = filt[2n] and Gp[n] = (Ge[n-1], Ge[n]):
//      even j=2a   : sum_s q[2s+1] * Gp[256+s-a].y
//      odd  j=2a+1 : sum_s q[2s]   * Gp[256+s-a].x
//    plus center tap fc = filt[511].
//    256 thr: 128 j-threads (2 a-values each: a, a+128) x 2 rowgroups x 4 rows
//    -> 16 FMA per 6 LDS.64 in the inner loop (LSU-balanced).
//  bids [128, 2176): CONSUMERS — fan-beam backprojection with half-turn
//    symmetry (view pair v, v+256 shares geometry via pixel point-mirror).
//    Gather table is a duplicated-PAIR table fr2[row][k]=(f[k],f[k+1]) padded
//    with zeros (bias 383.5) so each bilinear gather is ONE LDS.64 and no
//    validity masks are needed. Threads own x-quads -> STG.128 stores.
//    Consumers spin on the 4 producer flags they depend on (producers are the
//    lowest bids -> resident in wave 1 -> no deadlock).
// ============================================================================
__global__ __launch_bounds__(256)
void fused_kernel(const float* __restrict__ proj,
                  const float* __restrict__ w,
                  const float* __restrict__ filt,
                  float* __restrict__ out) {
    __shared__ __align__(16) float smem[8192];   // 32 KB, unioned by phase

    const int tid = threadIdx.x;
    const int bid = blockIdx.x;

    if (bid < N_PROD) {
        // ------------------------- PRODUCER -------------------------
        float (*q)[DETS] = (float (*)[DETS])smem;          // 8*512 floats
        float2* Gp       = (float2*)(smem + 8 * DETS);     // 512 float2

        const int row0 = bid * 8;

        for (int n = tid; n < DETS; n += 256) {
            float ge = filt[2 * n];
            float gm = (n >= 1) ? filt[2 * n - 2] : 0.0f;
            Gp[n] = make_float2(gm, ge);
        }
        for (int idx = tid; idx < 8 * DETS; idx += 256) {
            int r = idx >> 9;
            int c = idx & (DETS - 1);
            q[r][c] = proj[(row0 + r) * DETS + c] * w[c];
        }
        __syncthreads();

        const float fc   = filt[511];
        const int   jt   = tid & 127;        // a0 = jt, a1 = jt + 128
        const int   rowb = (tid >> 7) * 4;   // rowgroup

        float aE0[4] = {0, 0, 0, 0}, aO0[4] = {0, 0, 0, 0};
        float aE1[4] = {0, 0, 0, 0}, aO1[4] = {0, 0, 0, 0};

        const float2* gp0 = Gp + (256 - jt);     // gi0 = 256 - jt + s

#pragma unroll 4
        for (int s = 0; s < 256; ++s) {
            const float2 g0 = gp0[s];            // conflict-free (lanes consec.)
            const float2 g1 = gp0[s - 128];
            const float2 q0 = *(const float2*)&q[rowb + 0][2 * s];  // broadcast
            const float2 q1 = *(const float2*)&q[rowb + 1][2 * s];
            const float2 q2 = *(const float2*)&q[rowb + 2][2 * s];
            const float2 q3 = *(const float2*)&q[rowb + 3][2 * s];

            aE0[0] = fmaf(q0.y, g0.y, aE0[0]);  aO0[0] = fmaf(q0.x, g0.x, aO0[0]);
            aE1[0] = fmaf(q0.y, g1.y, aE1[0]);  aO1[0] = fmaf(q0.x, g1.x, aO1[0]);
            aE0[1] = fmaf(q1.y, g0.y, aE0[1]);  aO0[1] = fmaf(q1.x, g0.x, aO0[1]);
            aE1[1] = fmaf(q1.y, g1.y, aE1[1]);  aO1[1] = fmaf(q1.x, g1.x, aO1[1]);
            aE0[2] = fmaf(q2.y, g0.y, aE0[2]);  aO0[2] = fmaf(q2.x, g0.x, aO0[2]);
            aE1[2] = fmaf(q2.y, g1.y, aE1[2]);  aO1[2] = fmaf(q2.x, g1.x, aO1[2]);
            aE0[3] = fmaf(q3.y, g0.y, aE0[3]);  aO0[3] = fmaf(q3.x, g0.x, aO0[3]);
            aE1[3] = fmaf(q3.y, g1.y, aE1[3]);  aO1[3] = fmaf(q3.x, g1.x, aO1[3]);
        }

        const int j0 = 2 * jt;
        const int j1 = 2 * (jt + 128);
#pragma unroll
        for (int r = 0; r < 4; ++r) {
            float ve0 = fmaf(fc, q[rowb + r][j0],     aE0[r]);
            float vo0 = fmaf(fc, q[rowb + r][j0 + 1], aO0[r]);
            *(float2*)&g_filtered[(row0 + rowb + r) * DETS + j0] = make_float2(ve0, vo0);
            float ve1 = fmaf(fc, q[rowb + r][j1],     aE1[r]);
            float vo1 = fmaf(fc, q[rowb + r][j1 + 1], aO1[r]);
            *(float2*)&g_filtered[(row0 + rowb + r) * DETS + j1] = make_float2(ve1, vo1);
        }

        __syncthreads();
        __threadfence();
        if (tid == 0) atomicExch(&g_done[bid], 1);
        return;
    }

    // --------------------------- CONSUMER ---------------------------
    const int cid = bid - N_PROD;
    const int vp  = cid >> 3;     // view pair: v0 = vp, v1 = vp + 256
    const int yt  = cid & 7;      // y tile

    // wait for the 4 producer groups covering rows vp, vp+256, 512+vp, 768+vp
    if (tid < 4) {
        volatile int* f = g_done + (vp >> 3) + tid * 32;
        while (*f == 0) __nanosleep(64);
        __threadfence();
    }
    __syncthreads();

    float2 (*fr2)[1024] = (float2 (*)[1024])smem;   // 4 rows, 32 KB exactly

    // pass 1: plain values into .x  (row order: v0b0, v0b1, v1b0, v1b1)
    for (int idx = tid; idx < 4096; idx += 256) {
        const int row = idx >> 10;
        const int col = idx & 1023;
        const int vi  = row >> 1;
        const int b   = row & 1;
        const int c   = col - 128;
        float val = 0.0f;
        if ((unsigned)c < (unsigned)DETS)
            val = __ldcg(&g_filtered[(b * VIEWS + vp + vi * 256) * DETS + c]);
        fr2[row][col].x = val;
    }
    __syncthreads();
    // pass 2: neighbor value into .y
    for (int idx = tid; idx < 4096; idx += 256) {
        const int row = idx >> 10;
        const int col = idx & 1023;
        fr2[row][col].y = (col < 1023) ? fr2[row][col + 1].x : 0.0f;
    }

    const float beta = (float)dD_ANG * (float)vp;
    float sb, cb;
    sincosf(beta, &sb, &cb);
    __syncthreads();

    const float S2R  = (float)dS2R;
    const float DIMG = (float)dD_IMG;
    const float K    = (float)(dS2R / dVIRDET);
    const float Kcb  = K * cb;

    const int tx = tid & 63;   // x-quad: x = 4*tx + k
    const int ty = tid >> 6;   // y offset within group of 4 rows

    float A[4], B[4];
#pragma unroll
    for (int k = 0; k < 4; ++k) {
        float xs = ((float)(4 * tx + k) - 127.5f) * DIMG;
        A[k] = S2R - xs * cb;        // d = A - ys*sb
        B[k] = K * (xs * sb);        // num = ys*Kcb - B
    }

    const int ybase = yt * 32;
    const int bstr  = VIEWS * H_IMG * W_IMG;

    float* p0 = out + ((vp)       * H_IMG + (ybase + ty))       * W_IMG + 4 * tx;
    float* pm = out + ((vp + 256) * H_IMG + (255 - ybase - ty)) * W_IMG + (252 - 4 * tx);

#pragma unroll 2
    for (int i = 0; i < 8; ++i) {
        const float yv    = (float)(ybase + 4 * i + ty);
        const float ys    = (127.5f - yv) * DIMG;
        const float yssb  = ys * sb;
        const float ysKcb = ys * Kcb;

        float v00[4], v01[4], v10[4], v11[4];
#pragma unroll
        for (int k = 0; k < 4; ++k) {
            const float d   = A[k] - yssb;
            const float inv = __fdividef(1.0f, d);
            const float t   = fmaf(ysKcb - B[k], inv, 383.5f);  // +255.5 +128 pad
            float wg = S2R * inv;  wg *= wg;

            const float fl = floorf(t);
            const float h  = t - fl;
            const int   j  = (int)fl;                            // in [3, 763]

            const float2 g0 = fr2[0][j];   // (f[j], f[j+1]) in one LDS.64
            const float2 g1 = fr2[1][j];
            const float2 g2 = fr2[2][j];
            const float2 g3 = fr2[3][j];

            v00[k] = wg * fmaf(h, g0.y - g0.x, g0.x);
            v01[k] = wg * fmaf(h, g1.y - g1.x, g1.x);
            v10[k] = wg * fmaf(h, g2.y - g2.x, g2.x);
            v11[k] = wg * fmaf(h, g3.y - g3.x, g3.x);
        }

        *(float4*)(p0)        = make_float4(v00[0], v00[1], v00[2], v00[3]);
        *(float4*)(p0 + bstr) = make_float4(v01[0], v01[1], v01[2], v01[3]);
        // mirrored view: x reversed -> reversed components
        *(float4*)(pm)        = make_float4(v10[3], v10[2], v10[1], v10[0]);
        *(float4*)(pm + bstr) = make_float4(v11[3], v11[2], v11[1], v11[0]);

        p0 += 4 * W_IMG;
        pm -= 4 * W_IMG;
    }
}

extern "C" void kernel_launch(void* const* d_in, const int* in_sizes, int n_in,
                              void* d_out, int out_size) {
    const float* proj = (const float*)d_in[0];   // (2,1,512,512)
    const float* w    = (const float*)d_in[1];   // (1,1,1,512)
    const float* filt = (const float*)d_in[2];   // (1,1,1,1023)
    float* out = (float*)d_out;                  // (2,512,256,256)

    reset_kernel<<<1, 128>>>();
    fused_kernel<<<N_PROD + N_CONS, 256>>>(proj, w, filt, out);
}